// round 3
// baseline (speedup 1.0000x reference)
#include <cuda_runtime.h>
#include <cstdint>
#include <cfloat>

// MAM fully-connected:
//   out[m,n] = sum over splits s of ( max_b P(s,b) + min_b P(s,b) ) + bias[n]
//   P(s,b)[m,n] = sum_{k in block b of split s} x[m,k]*weight[n,k]
// K split into SPLITS=2 halves, ACCBLOCK=32 within each half.
//
// Kernel: 128x128 CTA tile, 256 threads, 8x8 micro-tile, K-tile = 32 (== ACCBLOCK).
// Two launches: pass 0 writes split-0 (max+min); pass 1 adds split-1 + bias.

#define TM 128
#define TN 128
#define TK 32
#define NTHREADS 256

__device__ __forceinline__ void cp_async16(uint32_t saddr, const void* g) {
    asm volatile("cp.async.cg.shared.global [%0], [%1], 16;\n" :: "r"(saddr), "l"(g));
}
__device__ __forceinline__ void cp_commit() {
    asm volatile("cp.async.commit_group;\n" ::);
}
__device__ __forceinline__ void cp_wait0() {
    asm volatile("cp.async.wait_group 0;\n" :: : "memory");
}

// Load one 128x32 fp32 tile (rows K-contiguous in global) into swizzled SMEM.
// SMEM row = 32 floats (128B). 16B chunk c of row r stored at chunk (c ^ ((r>>3)&7)).
__device__ __forceinline__ void prefetch_tile(float* sbase, const float* g, int ldK, int tid) {
#pragma unroll
    for (int p = 0; p < 4; ++p) {
        int idx = tid + p * NTHREADS;   // 0..1023
        int row = idx >> 3;             // 0..127
        int c   = idx & 7;              // chunk within row
        int cs  = c ^ ((row >> 3) & 7); // swizzled chunk
        uint32_t saddr = (uint32_t)__cvta_generic_to_shared(sbase + row * 32 + cs * 4);
        cp_async16(saddr, g + (size_t)row * ldK + c * 4);
    }
}

__global__ void __launch_bounds__(NTHREADS, 1)
mam_kernel(const float* __restrict__ x,
           const float* __restrict__ w,
           const float* __restrict__ bias,
           float* __restrict__ out,
           int M, int N, int K,
           int k_begin, int k_end,
           int final_pass)
{
    extern __shared__ float smem[];
    float* Abuf[2] = { smem,              smem + 2 * TM * TK };
    float* Bbuf[2] = { smem + TM * TK,    smem + 3 * TM * TK };

    const int tid = threadIdx.x;
    const int m0 = blockIdx.y * TM;
    const int n0 = blockIdx.x * TN;

    const int tm0 = (tid >> 4) << 3;   // 0,8,...,120
    const int tn0 = (tid & 15) << 3;   // 0,8,...,120

    // per-thread swizzle constants: rows tm0..tm0+7 share (row>>3)&7
    const int swA = (tm0 >> 3) & 7;
    const int swB = (tn0 >> 3) & 7;

    const float* gA = x + (size_t)m0 * K + k_begin;
    const float* gB = w + (size_t)n0 * K + k_begin;

    float acc[8][8], mx[8][8], mn[8][8];
#pragma unroll
    for (int i = 0; i < 8; ++i)
#pragma unroll
        for (int j = 0; j < 8; ++j) {
            acc[i][j] = 0.0f;
            mx[i][j] = -FLT_MAX;
            mn[i][j] =  FLT_MAX;
        }

    const int nt = (k_end - k_begin) / TK;   // 64 blocks per split

    // prologue: prefetch tile 0 into buffer 0
    prefetch_tile(Abuf[0], gA, K, tid);
    prefetch_tile(Bbuf[0], gB, K, tid);
    cp_commit();

    for (int t = 0; t < nt; ++t) {
        const int buf = t & 1;

        cp_wait0();            // tile t resident (each thread waits its own groups)
        __syncthreads();       // all threads' loads visible; prior compute done

        if (t + 1 < nt) {      // overlap next tile load with compute
            int kt = (t + 1) * TK;
            prefetch_tile(Abuf[buf ^ 1], gA + kt, K, tid);
            prefetch_tile(Bbuf[buf ^ 1], gB + kt, K, tid);
            cp_commit();
        }

        const float* A = Abuf[buf] + tm0 * 32;
        const float* B = Bbuf[buf] + tn0 * 32;

#pragma unroll 8
        for (int k = 0; k < TK; ++k) {
            const int cA = (((k >> 2) ^ swA) << 2) | (k & 3);
            const int cB = (((k >> 2) ^ swB) << 2) | (k & 3);
            float rA[8], rB[8];
#pragma unroll
            for (int i = 0; i < 8; ++i) rA[i] = A[i * 32 + cA];
#pragma unroll
            for (int j = 0; j < 8; ++j) rB[j] = B[j * 32 + cB];
#pragma unroll
            for (int i = 0; i < 8; ++i)
#pragma unroll
                for (int j = 0; j < 8; ++j)
                    acc[i][j] = fmaf(rA[i], rB[j], acc[i][j]);
        }

        // ACCBLOCK boundary (TK == 32): fold partial into running max/min, reset
#pragma unroll
        for (int i = 0; i < 8; ++i)
#pragma unroll
            for (int j = 0; j < 8; ++j) {
                mx[i][j] = fmaxf(mx[i][j], acc[i][j]);
                mn[i][j] = fminf(mn[i][j], acc[i][j]);
                acc[i][j] = 0.0f;
            }
        // no trailing barrier needed: next iteration's cp_wait0 + __syncthreads
        // orders buffer reuse (prefetch at iter t wrote buf^1, consumed at t+1)
        __syncthreads();
    }

    // epilogue
    float bval[8];
    if (final_pass) {
#pragma unroll
        for (int j = 0; j < 8; ++j) bval[j] = bias[n0 + tn0 + j];
    }

#pragma unroll
    for (int i = 0; i < 8; ++i) {
        size_t off = (size_t)(m0 + tm0 + i) * N + (n0 + tn0);
        float v[8];
#pragma unroll
        for (int j = 0; j < 8; ++j) v[j] = mx[i][j] + mn[i][j];
        if (final_pass) {
            float4 p0 = *(const float4*)(out + off);
            float4 p1 = *(const float4*)(out + off + 4);
            v[0] += p0.x + bval[0]; v[1] += p0.y + bval[1];
            v[2] += p0.z + bval[2]; v[3] += p0.w + bval[3];
            v[4] += p1.x + bval[4]; v[5] += p1.y + bval[5];
            v[6] += p1.z + bval[6]; v[7] += p1.w + bval[7];
        }
        *(float4*)(out + off)     = make_float4(v[0], v[1], v[2], v[3]);
        *(float4*)(out + off + 4) = make_float4(v[4], v[5], v[6], v[7]);
    }
}

extern "C" void kernel_launch(void* const* d_in, const int* in_sizes, int n_in,
                              void* d_out, int out_size) {
    const float* x    = (const float*)d_in[0];   // [M, K]
    const float* wgt  = (const float*)d_in[1];   // [N, K]
    const float* bias = (const float*)d_in[2];   // [N]
    float* out = (float*)d_out;                  // [M, N]

    const int N = in_sizes[2];
    const int K = in_sizes[1] / N;
    const int M = in_sizes[0] / K;

    // SPLITS = 2: sub = ceil(K/2); split ranges [0, sub) and [sub, K)
    const int sub = (K + 1) / 2;

    dim3 grid(N / TN, M / TM);
    dim3 block(NTHREADS);
    const size_t smem_bytes = 4 * TM * TK * sizeof(float);   // 64 KB (double-buffered A+B)

    cudaFuncSetAttribute(mam_kernel, cudaFuncAttributeMaxDynamicSharedMemorySize,
                         (int)smem_bytes);

    // pass 0: split 0, write (max+min)
    mam_kernel<<<grid, block, smem_bytes>>>(x, wgt, bias, out, M, N, K, 0, sub, 0);
    // pass 1: split 1, add previous + bias
    mam_kernel<<<grid, block, smem_bytes>>>(x, wgt, bias, out, M, N, K, sub, K, 1);
}

// round 4
// speedup vs baseline: 1.0006x; 1.0006x over previous
#include <cuda_runtime.h>
#include <cstdint>
#include <cfloat>

// MAM fully-connected:
//   out[m,n] = sum over splits s of ( max_b P(s,b) + min_b P(s,b) ) + bias[n]
//   P(s,b)[m,n] = sum_{k in block b of split s} x[m,k]*weight[n,k]
// K split into SPLITS=2 halves, ACCBLOCK=32 within each half.
//
// Kernel: 128x128 CTA tile, 256 threads, 8x8 micro-tile, K-tile = 32 (== ACCBLOCK).
// Two launches: pass 0 writes split-0 (max+min); pass 1 adds split-1 + bias.

#define TM 128
#define TN 128
#define TK 32
#define NTHREADS 256

__device__ __forceinline__ void cp_async16(uint32_t saddr, const void* g) {
    asm volatile("cp.async.cg.shared.global [%0], [%1], 16;\n" :: "r"(saddr), "l"(g));
}
__device__ __forceinline__ void cp_commit() {
    asm volatile("cp.async.commit_group;\n" ::);
}
__device__ __forceinline__ void cp_wait0() {
    asm volatile("cp.async.wait_group 0;\n" :: : "memory");
}

// Load one 128x32 fp32 tile (rows K-contiguous in global) into swizzled SMEM.
// SMEM row = 32 floats (128B). 16B chunk c of row r stored at chunk (c ^ ((r>>3)&7)).
__device__ __forceinline__ void prefetch_tile(float* sbase, const float* g, int ldK, int tid) {
#pragma unroll
    for (int p = 0; p < 4; ++p) {
        int idx = tid + p * NTHREADS;   // 0..1023
        int row = idx >> 3;             // 0..127
        int c   = idx & 7;              // chunk within row
        int cs  = c ^ ((row >> 3) & 7); // swizzled chunk
        uint32_t saddr = (uint32_t)__cvta_generic_to_shared(sbase + row * 32 + cs * 4);
        cp_async16(saddr, g + (size_t)row * ldK + c * 4);
    }
}

__global__ void __launch_bounds__(NTHREADS, 1)
mam_kernel(const float* __restrict__ x,
           const float* __restrict__ w,
           const float* __restrict__ bias,
           float* __restrict__ out,
           int M, int N, int K,
           int k_begin, int k_end,
           int final_pass)
{
    extern __shared__ float smem[];
    float* Abuf[2] = { smem,              smem + 2 * TM * TK };
    float* Bbuf[2] = { smem + TM * TK,    smem + 3 * TM * TK };

    const int tid = threadIdx.x;
    const int m0 = blockIdx.y * TM;
    const int n0 = blockIdx.x * TN;

    const int tm0 = (tid >> 4) << 3;   // 0,8,...,120
    const int tn0 = (tid & 15) << 3;   // 0,8,...,120

    // per-thread swizzle constants: rows tm0..tm0+7 share (row>>3)&7
    const int swA = (tm0 >> 3) & 7;
    const int swB = (tn0 >> 3) & 7;

    const float* gA = x + (size_t)m0 * K + k_begin;
    const float* gB = w + (size_t)n0 * K + k_begin;

    float acc[8][8], mx[8][8], mn[8][8];
#pragma unroll
    for (int i = 0; i < 8; ++i)
#pragma unroll
        for (int j = 0; j < 8; ++j) {
            acc[i][j] = 0.0f;
            mx[i][j] = -FLT_MAX;
            mn[i][j] =  FLT_MAX;
        }

    const int nt = (k_end - k_begin) / TK;   // 64 blocks per split

    // prologue: prefetch tile 0 into buffer 0
    prefetch_tile(Abuf[0], gA, K, tid);
    prefetch_tile(Bbuf[0], gB, K, tid);
    cp_commit();

    for (int t = 0; t < nt; ++t) {
        const int buf = t & 1;

        cp_wait0();            // tile t resident (each thread waits its own groups)
        __syncthreads();       // all threads' loads visible; prior compute done

        if (t + 1 < nt) {      // overlap next tile load with compute
            int kt = (t + 1) * TK;
            prefetch_tile(Abuf[buf ^ 1], gA + kt, K, tid);
            prefetch_tile(Bbuf[buf ^ 1], gB + kt, K, tid);
            cp_commit();
        }

        const float* A = Abuf[buf] + tm0 * 32;
        const float* B = Bbuf[buf] + tn0 * 32;

#pragma unroll 8
        for (int k = 0; k < TK; ++k) {
            const int cA = (((k >> 2) ^ swA) << 2) | (k & 3);
            const int cB = (((k >> 2) ^ swB) << 2) | (k & 3);
            float rA[8], rB[8];
#pragma unroll
            for (int i = 0; i < 8; ++i) rA[i] = A[i * 32 + cA];
#pragma unroll
            for (int j = 0; j < 8; ++j) rB[j] = B[j * 32 + cB];
#pragma unroll
            for (int i = 0; i < 8; ++i)
#pragma unroll
                for (int j = 0; j < 8; ++j)
                    acc[i][j] = fmaf(rA[i], rB[j], acc[i][j]);
        }

        // ACCBLOCK boundary (TK == 32): fold partial into running max/min, reset
#pragma unroll
        for (int i = 0; i < 8; ++i)
#pragma unroll
            for (int j = 0; j < 8; ++j) {
                mx[i][j] = fmaxf(mx[i][j], acc[i][j]);
                mn[i][j] = fminf(mn[i][j], acc[i][j]);
                acc[i][j] = 0.0f;
            }
        // no trailing barrier needed: next iteration's cp_wait0 + __syncthreads
        // orders buffer reuse (prefetch at iter t wrote buf^1, consumed at t+1)
        __syncthreads();
    }

    // epilogue
    float bval[8];
    if (final_pass) {
#pragma unroll
        for (int j = 0; j < 8; ++j) bval[j] = bias[n0 + tn0 + j];
    }

#pragma unroll
    for (int i = 0; i < 8; ++i) {
        size_t off = (size_t)(m0 + tm0 + i) * N + (n0 + tn0);
        float v[8];
#pragma unroll
        for (int j = 0; j < 8; ++j) v[j] = mx[i][j] + mn[i][j];
        if (final_pass) {
            float4 p0 = *(const float4*)(out + off);
            float4 p1 = *(const float4*)(out + off + 4);
            v[0] += p0.x + bval[0]; v[1] += p0.y + bval[1];
            v[2] += p0.z + bval[2]; v[3] += p0.w + bval[3];
            v[4] += p1.x + bval[4]; v[5] += p1.y + bval[5];
            v[6] += p1.z + bval[6]; v[7] += p1.w + bval[7];
        }
        *(float4*)(out + off)     = make_float4(v[0], v[1], v[2], v[3]);
        *(float4*)(out + off + 4) = make_float4(v[4], v[5], v[6], v[7]);
    }
}

extern "C" void kernel_launch(void* const* d_in, const int* in_sizes, int n_in,
                              void* d_out, int out_size) {
    const float* x    = (const float*)d_in[0];   // [M, K]
    const float* wgt  = (const float*)d_in[1];   // [N, K]
    const float* bias = (const float*)d_in[2];   // [N]
    float* out = (float*)d_out;                  // [M, N]

    const int N = in_sizes[2];
    const int K = in_sizes[1] / N;
    const int M = in_sizes[0] / K;

    // SPLITS = 2: sub = ceil(K/2); split ranges [0, sub) and [sub, K)
    const int sub = (K + 1) / 2;

    dim3 grid(N / TN, M / TM);
    dim3 block(NTHREADS);
    const size_t smem_bytes = 4 * TM * TK * sizeof(float);   // 64 KB (double-buffered A+B)

    cudaFuncSetAttribute(mam_kernel, cudaFuncAttributeMaxDynamicSharedMemorySize,
                         (int)smem_bytes);

    // pass 0: split 0, write (max+min)
    mam_kernel<<<grid, block, smem_bytes>>>(x, wgt, bias, out, M, N, K, 0, sub, 0);
    // pass 1: split 1, add previous + bias
    mam_kernel<<<grid, block, smem_bytes>>>(x, wgt, bias, out, M, N, K, sub, K, 1);
}